// round 14
// baseline (speedup 1.0000x reference)
#include <cuda_runtime.h>

// GraphAggregation: out[b][d] = mean over 196 nodes of in[b][n*4 + d]
// in:  (B, 784) float32   out: (B, 4) float32
//
// HBM-streaming bound (416 MB). R11 (256-bit LDG, 2 rows/warp) = 6912 GB/s.
// This round: 256-bit LDG + 4 ADJACENT rows per warp. A row-quad is 392
// aligned 32B chunks: 12 full-warp LDG.256 front-batched + one 8-lane tail
// (chunks 384..391, all in row 3). Per-row ownership via predicated adds.

struct __align__(32) f8 { float4 a, b; };

__device__ __forceinline__ f8 ldg256(const f8* p) {
    f8 r;
    asm volatile("ld.global.nc.v8.f32 {%0,%1,%2,%3,%4,%5,%6,%7}, [%8];"
                 : "=f"(r.a.x), "=f"(r.a.y), "=f"(r.a.z), "=f"(r.a.w),
                   "=f"(r.b.x), "=f"(r.b.y), "=f"(r.b.z), "=f"(r.b.w)
                 : "l"(p));
    return r;
}

__global__ void __launch_bounds__(256, 2)
graph_agg_kernel(const f8* __restrict__ in, float4* __restrict__ out, int B4)
{
    const int lane = threadIdx.x & 31;
    const int warp = (int)((blockIdx.x * (unsigned)blockDim.x + threadIdx.x) >> 5);
    if (warp >= B4) return;              // B4 = B/4 row-quads

    const int r = warp * 4;
    const f8* base = in + (size_t)r * 98;    // 4*98 = 392 f8-chunks

    // ---- front-batched independent 256-bit loads: 12 full + 8-lane tail ----
    f8 v[12];
    #pragma unroll
    for (int k = 0; k < 12; ++k) v[k] = ldg256(base + k * 32 + lane);

    f8 t;
    t.a = make_float4(0.f, 0.f, 0.f, 0.f);
    t.b = make_float4(0.f, 0.f, 0.f, 0.f);
    if (lane < 8) t = ldg256(base + 384 + lane);   // chunks 384..391, row 3

    // ---- per-row accumulation (row j spans chunks [98j, 98j+98)) ----
    float ax[4] = {0.f,0.f,0.f,0.f};
    float ay[4] = {0.f,0.f,0.f,0.f};
    float az[4] = {0.f,0.f,0.f,0.f};
    float aw[4] = {0.f,0.f,0.f,0.f};

    #pragma unroll
    for (int k = 0; k < 12; ++k) {
        const int idx = k * 32 + lane;       // chunk index 0..383
        const int row = idx / 98;            // 0..3
        const float sx = v[k].a.x + v[k].b.x;
        const float sy = v[k].a.y + v[k].b.y;
        const float sz = v[k].a.z + v[k].b.z;
        const float sw = v[k].a.w + v[k].b.w;
        #pragma unroll
        for (int j = 0; j < 4; ++j) {
            ax[j] += (row == j) ? sx : 0.f;
            ay[j] += (row == j) ? sy : 0.f;
            az[j] += (row == j) ? sz : 0.f;
            aw[j] += (row == j) ? sw : 0.f;
        }
    }
    // tail: all in row 3
    ax[3] += t.a.x + t.b.x;
    ay[3] += t.a.y + t.b.y;
    az[3] += t.a.z + t.b.z;
    aw[3] += t.a.w + t.b.w;

    // ---- butterfly reductions (4 rows x 4 components) ----
    #pragma unroll
    for (int off = 16; off > 0; off >>= 1) {
        #pragma unroll
        for (int j = 0; j < 4; ++j) {
            ax[j] += __shfl_xor_sync(0xffffffffu, ax[j], off);
            ay[j] += __shfl_xor_sync(0xffffffffu, ay[j], off);
            az[j] += __shfl_xor_sync(0xffffffffu, az[j], off);
            aw[j] += __shfl_xor_sync(0xffffffffu, aw[j], off);
        }
    }

    if (lane == 0) {
        const float s = 1.0f / 196.0f;
        #pragma unroll
        for (int j = 0; j < 4; ++j)
            out[r + j] = make_float4(ax[j] * s, ay[j] * s, az[j] * s, aw[j] * s);
    }
}

extern "C" void kernel_launch(void* const* d_in, const int* in_sizes, int n_in,
                              void* d_out, int out_size)
{
    const f8* in      = (const f8*)d_in[0];
    float4*   out     = (float4*)d_out;
    const int B  = in_sizes[0] / 784;         // 131072 (divisible by 4)
    const int B4 = B / 4;                     // row-quads: 32768

    const int threads = 256;                  // 8 warps/block -> 32 rows/block
    const int blocks  = (B4 + 7) / 8;         // 4096

    graph_agg_kernel<<<blocks, threads>>>(in, out, B4);
}

// round 16
// speedup vs baseline: 1.0107x; 1.0107x over previous
#include <cuda_runtime.h>

// GraphAggregation: out[b][d] = mean over 196 nodes of in[b][n*4 + d]
// in:  (B, 784) float32   out: (B, 4) float32
//
// FINAL-candidate: R11 (best measured: 6912 GB/s, 60.3us) + occupancy bump.
// R11 compiled to 63 regs; launch_bounds(256,4) caps at 64 -> same codegen
// but 4 CTAs/SM (32 warps) instead of 3: +33% SM-level outstanding loads.
//  - 256-bit LDG (halves LSU instruction count vs float4 -> +2.8% measured)
//  - each warp owns 2 ADJACENT rows (page/TLB locality)
//  - 6 full-warp LDG.256 + merged 4-lane tail, front-batched
//  - short butterfly epilogue, fully hidden behind other warps' loads

struct __align__(32) f8 { float4 a, b; };

__device__ __forceinline__ f8 ldg256(const f8* p) {
    f8 r;
    asm volatile("ld.global.nc.v8.f32 {%0,%1,%2,%3,%4,%5,%6,%7}, [%8];"
                 : "=f"(r.a.x), "=f"(r.a.y), "=f"(r.a.z), "=f"(r.a.w),
                   "=f"(r.b.x), "=f"(r.b.y), "=f"(r.b.z), "=f"(r.b.w)
                 : "l"(p));
    return r;
}

__global__ void __launch_bounds__(256, 4)
graph_agg_kernel(const f8* __restrict__ in, float4* __restrict__ out, int B2)
{
    const int lane = threadIdx.x & 31;
    const int warp = (int)((blockIdx.x * (unsigned)blockDim.x + threadIdx.x) >> 5);
    if (warp >= B2) return;              // B2 = B/2 row-pairs

    const int r = warp * 2;
    const f8* rowA = in + (size_t)r * 98;    // 98 f8-chunks per row
    const f8* rowB = rowA + 98;

    // ---- front-batched independent 256-bit loads ----
    f8 va[3], vb[3];
    #pragma unroll
    for (int k = 0; k < 3; ++k) va[k] = ldg256(rowA + k * 32 + lane);
    #pragma unroll
    for (int k = 0; k < 3; ++k) vb[k] = ldg256(rowB + k * 32 + lane);

    // merged tail: lanes 0-1 load rowA chunks 96,97; lanes 2-3 rowB 96,97
    f8 t;
    t.a = make_float4(0.f, 0.f, 0.f, 0.f);
    t.b = make_float4(0.f, 0.f, 0.f, 0.f);
    if (lane < 4) {
        const f8* tp = (lane < 2) ? (rowA + 96 + lane) : (rowB + 94 + lane);
        t = ldg256(tp);
    }

    // ---- accumulate (each f8 = two node vectors) ----
    float ax = 0.f, ay = 0.f, az = 0.f, aw = 0.f;
    float bx = 0.f, by = 0.f, bz = 0.f, bw = 0.f;
    #pragma unroll
    for (int k = 0; k < 3; ++k) {
        ax += va[k].a.x + va[k].b.x;
        ay += va[k].a.y + va[k].b.y;
        az += va[k].a.z + va[k].b.z;
        aw += va[k].a.w + va[k].b.w;
        bx += vb[k].a.x + vb[k].b.x;
        by += vb[k].a.y + vb[k].b.y;
        bz += vb[k].a.z + vb[k].b.z;
        bw += vb[k].a.w + vb[k].b.w;
    }
    if (lane < 2) {
        ax += t.a.x + t.b.x; ay += t.a.y + t.b.y;
        az += t.a.z + t.b.z; aw += t.a.w + t.b.w;
    } else {
        bx += t.a.x + t.b.x; by += t.a.y + t.b.y;
        bz += t.a.z + t.b.z; bw += t.a.w + t.b.w;
    }

    // ---- butterfly reductions ----
    #pragma unroll
    for (int off = 16; off > 0; off >>= 1) {
        ax += __shfl_xor_sync(0xffffffffu, ax, off);
        ay += __shfl_xor_sync(0xffffffffu, ay, off);
        az += __shfl_xor_sync(0xffffffffu, az, off);
        aw += __shfl_xor_sync(0xffffffffu, aw, off);
        bx += __shfl_xor_sync(0xffffffffu, bx, off);
        by += __shfl_xor_sync(0xffffffffu, by, off);
        bz += __shfl_xor_sync(0xffffffffu, bz, off);
        bw += __shfl_xor_sync(0xffffffffu, bw, off);
    }

    if (lane == 0) {
        const float s = 1.0f / 196.0f;
        out[r]     = make_float4(ax * s, ay * s, az * s, aw * s);
        out[r + 1] = make_float4(bx * s, by * s, bz * s, bw * s);
    }
}

extern "C" void kernel_launch(void* const* d_in, const int* in_sizes, int n_in,
                              void* d_out, int out_size)
{
    const f8* in      = (const f8*)d_in[0];
    float4*   out     = (float4*)d_out;
    const int B  = in_sizes[0] / 784;         // 131072 (even)
    const int B2 = B / 2;                     // row-pairs

    const int threads = 256;                  // 8 warps/block -> 16 rows/block
    const int blocks  = (B2 + 7) / 8;         // 8192

    graph_agg_kernel<<<blocks, threads>>>(in, out, B2);
}

// round 17
// speedup vs baseline: 1.0206x; 1.0098x over previous
#include <cuda_runtime.h>

// GraphAggregation: out[b][d] = mean over 196 nodes of in[b][n*4 + d]
// in:  (B, 784) float32   out: (B, 4) float32
//
// FINAL (= Round-11 kernel, best measured: 60.3us ncu, 6912 GB/s = 86.4% of
// HBM spec). HBM-streaming bound; traffic equals the 416 MB footprint.
// Levers validated across the session:
//  - 256-bit LDG (ld.global.nc.v8.f32): halves LSU instruction count vs
//    float4 -> +2.8% measured throughput (LSU queue-accept was a co-limiter)
//  - 2 ADJACENT rows per warp: page/TLB locality (grid-stride cost +230MB
//    of page-walk DRAM traffic in R2); 7 front-batched independent loads
//  - launch_bounds(256,3): 63 regs, whole load batch in flight
// Falsified levers: 4-row batching (epilogue-exposure regression), occupancy
// bump via (256,4) (achieved occ unchanged), persistent grid (TLB thrash).

struct __align__(32) f8 { float4 a, b; };

__device__ __forceinline__ f8 ldg256(const f8* p) {
    f8 r;
    asm volatile("ld.global.nc.v8.f32 {%0,%1,%2,%3,%4,%5,%6,%7}, [%8];"
                 : "=f"(r.a.x), "=f"(r.a.y), "=f"(r.a.z), "=f"(r.a.w),
                   "=f"(r.b.x), "=f"(r.b.y), "=f"(r.b.z), "=f"(r.b.w)
                 : "l"(p));
    return r;
}

__global__ void __launch_bounds__(256, 3)
graph_agg_kernel(const f8* __restrict__ in, float4* __restrict__ out, int B2)
{
    const int lane = threadIdx.x & 31;
    const int warp = (int)((blockIdx.x * (unsigned)blockDim.x + threadIdx.x) >> 5);
    if (warp >= B2) return;              // B2 = B/2 row-pairs

    const int r = warp * 2;
    const f8* rowA = in + (size_t)r * 98;    // 98 f8-chunks per row
    const f8* rowB = rowA + 98;

    // ---- front-batched independent 256-bit loads ----
    f8 va[3], vb[3];
    #pragma unroll
    for (int k = 0; k < 3; ++k) va[k] = ldg256(rowA + k * 32 + lane);
    #pragma unroll
    for (int k = 0; k < 3; ++k) vb[k] = ldg256(rowB + k * 32 + lane);

    // merged tail: lanes 0-1 load rowA chunks 96,97; lanes 2-3 rowB 96,97
    f8 t;
    t.a = make_float4(0.f, 0.f, 0.f, 0.f);
    t.b = make_float4(0.f, 0.f, 0.f, 0.f);
    if (lane < 4) {
        const f8* tp = (lane < 2) ? (rowA + 96 + lane) : (rowB + 94 + lane);
        t = ldg256(tp);
    }

    // ---- accumulate (each f8 = two node vectors) ----
    float ax = 0.f, ay = 0.f, az = 0.f, aw = 0.f;
    float bx = 0.f, by = 0.f, bz = 0.f, bw = 0.f;
    #pragma unroll
    for (int k = 0; k < 3; ++k) {
        ax += va[k].a.x + va[k].b.x;
        ay += va[k].a.y + va[k].b.y;
        az += va[k].a.z + va[k].b.z;
        aw += va[k].a.w + va[k].b.w;
        bx += vb[k].a.x + vb[k].b.x;
        by += vb[k].a.y + vb[k].b.y;
        bz += vb[k].a.z + vb[k].b.z;
        bw += vb[k].a.w + vb[k].b.w;
    }
    if (lane < 2) {
        ax += t.a.x + t.b.x; ay += t.a.y + t.b.y;
        az += t.a.z + t.b.z; aw += t.a.w + t.b.w;
    } else {
        bx += t.a.x + t.b.x; by += t.a.y + t.b.y;
        bz += t.a.z + t.b.z; bw += t.a.w + t.b.w;
    }

    // ---- butterfly reductions ----
    #pragma unroll
    for (int off = 16; off > 0; off >>= 1) {
        ax += __shfl_xor_sync(0xffffffffu, ax, off);
        ay += __shfl_xor_sync(0xffffffffu, ay, off);
        az += __shfl_xor_sync(0xffffffffu, az, off);
        aw += __shfl_xor_sync(0xffffffffu, aw, off);
        bx += __shfl_xor_sync(0xffffffffu, bx, off);
        by += __shfl_xor_sync(0xffffffffu, by, off);
        bz += __shfl_xor_sync(0xffffffffu, bz, off);
        bw += __shfl_xor_sync(0xffffffffu, bw, off);
    }

    if (lane == 0) {
        const float s = 1.0f / 196.0f;
        out[r]     = make_float4(ax * s, ay * s, az * s, aw * s);
        out[r + 1] = make_float4(bx * s, by * s, bz * s, bw * s);
    }
}

extern "C" void kernel_launch(void* const* d_in, const int* in_sizes, int n_in,
                              void* d_out, int out_size)
{
    const f8* in      = (const f8*)d_in[0];
    float4*   out     = (float4*)d_out;
    const int B  = in_sizes[0] / 784;         // 131072 (even)
    const int B2 = B / 2;                     // row-pairs

    const int threads = 256;                  // 8 warps/block -> 16 rows/block
    const int blocks  = (B2 + 7) / 8;         // 8192

    graph_agg_kernel<<<blocks, threads>>>(in, out, B2);
}